// round 15
// baseline (speedup 1.0000x reference)
#include <cuda_runtime.h>
#include <cuda_fp16.h>
#include <cstdint>
#include <math.h>

#define NN 16
#define TT 800
#define FF 90
#define SS 128
#define LL 200
#define NEGF (-1e30f)

// per-utterance scores scratch (device globals: no allocation allowed)
__device__ float g_den[NN];
__device__ float g_num[NN];

// blocks 0..7:   den CTA, 256 threads = 2 independent 128-thread groups;
//                group g runs utterance b + 8g. fp16 math (E column = 64
//                regs/thread, so 2 warps/SMSP fit without spilling). Both
//                groups share one __syncthreads; their latency windows
//                interleave on the SMSPs. Freeze-by-register for nf skew.
// blocks 8..23:  num for utterance b-8. 128 active threads, 2 states/thread.
__global__ __launch_bounds__(256, 1)
void mmi_forward(const float* __restrict__ nnet,   // [N, T, F] log-softmax
                 const int*   __restrict__ sup,    // [N, 3]
                 const float* __restrict__ trans,  // [S, S]
                 const int*   __restrict__ dlab,   // [S]
                 const int*   __restrict__ nlab,   // [N, L]
                 const int*   __restrict__ nlens)  // [N]
{
    __shared__ __align__(16) __half sh_vh[2][2][SS];   // [group][buf][state]
    __shared__ unsigned sh_wmax[2][2][4];              // [group][buf][warp]
    __shared__ float sh_wsum[2][4];
    __shared__ float sh_a[2][LL + 8];

    const int tid = threadIdx.x;
    const int b   = blockIdx.x;

    if (b < 8) {
        // ======= denominator forward (scaled fp16 linear space), dual utt =====
        const int g    = tid >> 7;          // group 0 or 1
        const int lt   = tid & 127;         // lane within group
        const int n    = b + 8 * g;         // utterance for this group
        const int nf   = sup[n * 3 + 2];
        const int nfo  = sup[(b + 8 * (1 - g)) * 3 + 2];
        const int nfMax = (nf > nfo) ? nf : nfo;
        const int s    = lt;                // output state
        const int lane = lt & 31;
        const int wrp  = lt >> 5;

        // Full E column (128 k-values) in fp16, packed half2 (64 regs).
        half2 E2h[64];
        #pragma unroll 8
        for (int j = 0; j < 64; ++j) {
            E2h[j] = __floats2half2_rn(expf(trans[(2 * j) * SS + s]),
                                       expf(trans[(2 * j + 1) * SS + s]));
        }
        const int lab = dlab[s];
        const float* lp_base = nnet + (long long)n * TT * FF + lab;
        float lp  = __ldg(lp_base);                          // t = 0
        float lp1 = __ldg(lp_base + FF);                     // t = 1

        // init: stored v = true v * 2^-7 (anchor 2^-7); Mexp starts at 7
        __half vprev = __float2half_rn((s == 0) ? 0.0078125f : 0.0f);
        sh_vh[g][0][s] = vprev;
        if (lt < 4) {
            sh_wmax[g][0][lt] = 8u << 10;   // fp16 bits of 2^-7 -> sigma = 1
            sh_wmax[g][1][lt] = 8u << 10;
        }
        __syncthreads();

        int cur  = 0;
        int Mexp = 7;

        #pragma unroll 2
        for (int t = 0; t < nfMax; ++t) {
            // even steps: exact 2^k rescale keyed to the group max written by
            // the previous (odd) step; odd steps: sigma = 1.
            float ps;
            int   dM = 0;
            if ((t & 1) == 0) {
                unsigned m = sh_wmax[g][cur][0];
                m = max(m, sh_wmax[g][cur][1]);
                m = max(m, sh_wmax[g][cur][2]);
                m = max(m, sh_wmax[g][cur][3]);
                const int   eh    = (int)(m >> 10);         // fp16 biased exp
                const float sigma = __uint_as_float((unsigned)(135 - eh) << 23);
                dM = eh - 8;
                ps = __expf(lp) * sigma;
            } else {
                ps = __expf(lp);
            }
            const __half ps_h = __float2half_rn(ps);   // off critical path

            const int   tn   = (t + 2 < TT) ? (t + 2) : (TT - 1);
            const float lpn2 = __ldg(lp_base + (long long)tn * FF); // prefetch

            const uint4* vp = reinterpret_cast<const uint4*>(&sh_vh[g][cur][0]);

            // 64 HFMA2 across 4 half2 accumulators
            half2 a0 = __float2half2_rn(0.f), a1 = a0, a2 = a0, a3 = a0;
            #pragma unroll
            for (int gg = 0; gg < 2; ++gg) {
                uint4 q[8];
                #pragma unroll
                for (int i = 0; i < 8; ++i) q[i] = vp[8 * gg + i];
                #pragma unroll
                for (int i = 0; i < 8; ++i) {
                    const int bb = (8 * gg + i) * 4;
                    const half2 v0 = *reinterpret_cast<const half2*>(&q[i].x);
                    const half2 v1 = *reinterpret_cast<const half2*>(&q[i].y);
                    const half2 v2 = *reinterpret_cast<const half2*>(&q[i].z);
                    const half2 v3 = *reinterpret_cast<const half2*>(&q[i].w);
                    a0 = __hfma2(v0, E2h[bb + 0], a0);
                    a1 = __hfma2(v1, E2h[bb + 1], a1);
                    a2 = __hfma2(v2, E2h[bb + 2], a2);
                    a3 = __hfma2(v3, E2h[bb + 3], a3);
                }
            }
            // all-half epilogue: tree -> hmul -> freeze-select -> store
            const half2 s01 = __hadd2(a0, a1);
            const half2 s23 = __hadd2(a2, a3);
            const half2 sal = __hadd2(s01, s23);
            const __half hsum = __hadd(__low2half(sal), __high2half(sal));
            const __half accv = __hmul(hsum, ps_h);

            const bool act = (t < nf);
            const __half store = act ? accv : vprev;   // frozen frames keep v
            Mexp += act ? dM : 0;
            vprev = store;
            sh_vh[g][cur ^ 1][s] = store;

            if (t & 1) {   // odd steps: publish group max for next even step
                const unsigned hb = (unsigned)__half_as_ushort(store);
                const unsigned wm = __reduce_max_sync(0xffffffffu, hb);
                if (lane == 0) sh_wmax[g][cur ^ 1][wrp] = wm;
            }

            lp  = lp1;
            lp1 = lpn2;
            __syncthreads();
            cur ^= 1;
        }

        // den = Mexp*ln2 + log(sum stored v)
        {
            float v = __half2float(sh_vh[g][cur][s]);
            #pragma unroll
            for (int o = 16; o; o >>= 1) v += __shfl_xor_sync(0xffffffffu, v, o);
            if (lane == 0) sh_wsum[g][wrp] = v;
        }
        __syncthreads();
        if (lt == 0) {
            const float sv = sh_wsum[g][0] + sh_wsum[g][1] +
                             sh_wsum[g][2] + sh_wsum[g][3];
            g_den[n] = (float)((double)Mexp * 0.6931471805599453 +
                               (double)logf(sv));
        }
    } else {
        // ============ numerator forward (log space), 2 states/thread ==========
        if (tid >= 128) return;
        const int n  = b - 8;
        const int nf = sup[n * 3 + 2];
        const int qi = nlens[n];
        const int i  = tid;                 // 0..127; active i < 100

        // thread i owns states l0 = 2i+1 and l1 = 2i+2
        const float* lpb0 = nnet;  // dummy init
        const float* lpb1 = nnet;
        float lpA = 0.f, lpA1 = 0.f, lpB = 0.f, lpB1 = 0.f;

        if (i < 100) {
            const long long base = (long long)n * TT * FF;
            lpb0 = nnet + base + nlab[n * LL + 2 * i];       // emit for l0
            lpb1 = nnet + base + nlab[n * LL + 2 * i + 1];   // emit for l1
            lpA  = __ldg(lpb0);       lpB  = __ldg(lpb1);
            lpA1 = __ldg(lpb0 + FF);  lpB1 = __ldg(lpb1 + FF);
        }
        for (int j = i; j <= LL; j += 128) {
            sh_a[0][j] = (j == 0) ? 0.0f : NEGF;
            sh_a[1][j] = NEGF;
        }
        int cur = 0;
        __syncthreads();

        for (int t = 0; t < nf; ++t) {
            if (i < 100) {
                const float am = sh_a[cur][2 * i];       // old alpha[l0-1]
                const float a0 = sh_a[cur][2 * i + 1];   // old alpha[l0]
                const float a1 = sh_a[cur][2 * i + 2];   // old alpha[l1]

                const float h0 = fmaxf(a0, am), l0v = fminf(a0, am);
                const float nv0 = h0 + __logf(1.0f + __expf(l0v - h0)) + lpA;
                const float h1 = fmaxf(a1, a0), l1v = fminf(a1, a0);
                const float nv1 = h1 + __logf(1.0f + __expf(l1v - h1)) + lpB;

                const int   tn = (t + 2 < TT) ? (t + 2) : (TT - 1);
                const float pA = __ldg(lpb0 + (long long)tn * FF);
                const float pB = __ldg(lpb1 + (long long)tn * FF);

                sh_a[cur ^ 1][2 * i + 1] = nv0;
                sh_a[cur ^ 1][2 * i + 2] = nv1;
                if (i == 0) sh_a[cur ^ 1][0] = NEGF;     // alpha[0] = NEG each step
                lpA = lpA1; lpA1 = pA;
                lpB = lpB1; lpB1 = pB;
            }
            __syncthreads();
            cur ^= 1;
        }
        if (i == 0) g_num[n] = sh_a[cur][qi];
    }
}

__global__ void mmi_finalize(const int* __restrict__ sup, float* __restrict__ out)
{
    const int tid = threadIdx.x;  // 32 threads
    float tot = 0.f, fr = 0.f, af = 0.f;
    if (tid < NN) {
        const int nf = sup[tid * 3 + 2];
        const float t = g_num[tid] - g_den[tid];
        const bool fin = isfinite(t) && (t > 0.5f * NEGF);
        tot = fin ? t : 0.f;
        fr  = fin ? (float)nf : 0.f;
        af  = (float)nf;
    }
    #pragma unroll
    for (int o = 16; o; o >>= 1) {
        tot += __shfl_xor_sync(0xffffffffu, tot, o);
        fr  += __shfl_xor_sync(0xffffffffu, fr, o);
        af  += __shfl_xor_sync(0xffffffffu, af, o);
    }
    if (tid == 0) {
        out[0] = tot;
        out[1] = fr;
        out[2] = af;
    }
}

extern "C" void kernel_launch(void* const* d_in, const int* in_sizes, int n_in,
                              void* d_out, int out_size)
{
    const float* nnet  = (const float*)d_in[0];
    const int*   sup   = (const int*)  d_in[1];
    const float* trans = (const float*)d_in[2];
    const int*   dlab  = (const int*)  d_in[3];
    const int*   nlab  = (const int*)  d_in[4];
    const int*   nlens = (const int*)  d_in[5];

    mmi_forward<<<24, 256>>>(nnet, sup, trans, dlab, nlab, nlens);
    mmi_finalize<<<1, 32>>>(sup, (float*)d_out);
}

// round 16
// speedup vs baseline: 1.2308x; 1.2308x over previous
#include <cuda_runtime.h>
#include <cuda_fp16.h>
#include <cstdint>
#include <math.h>

#define NN 16
#define TT 800
#define FF 90
#define SS 128
#define LL 200
#define NEGF (-1e30f)

// per-utterance scores scratch (device globals: no allocation allowed)
__device__ float g_den[NN];
__device__ float g_num[NN];

// blocks 0..15:  den for utterance b. 256 threads: 2 threads per state
//                (K-split halves), fp16 math, 2 warps/SMSP so the second
//                warp's HFMA2 stream fills the first's LDS/tail windows.
//                Exact 2^k rescale anchored at 2^-7; block max via fp16-bit
//                REDUX on odd steps, consumed on even steps.
// blocks 16..31: num for utterance b-16. 128 active threads, 2 states/thread.
__global__ __launch_bounds__(256, 1)
void mmi_forward(const float* __restrict__ nnet,   // [N, T, F] log-softmax
                 const int*   __restrict__ sup,    // [N, 3]
                 const float* __restrict__ trans,  // [S, S]
                 const int*   __restrict__ dlab,   // [S]
                 const int*   __restrict__ nlab,   // [N, L]
                 const int*   __restrict__ nlens)  // [N]
{
    // v stored as two 64-half segments at half-offsets 0 and 72 (144B skew:
    // even-lane and odd-lane broadcast LDS.128 hit disjoint bank groups)
    __shared__ __align__(16) __half sh_vh[2][144];
    __shared__ unsigned sh_wmax[2][8];              // per-warp fp16-bit maxes
    __shared__ float sh_wsum[4];
    __shared__ float sh_a[2][LL + 8];

    const int tid = threadIdx.x;
    const int b   = blockIdx.x;

    if (b < NN) {
        // ======= denominator forward (scaled fp16 linear space) ===============
        const int n    = b;
        const int nf   = sup[n * 3 + 2];
        const int s    = tid >> 1;          // output state (2 threads/state)
        const int kh   = tid & 1;           // K half: [kh*64, kh*64+64)
        const int pidx = (s >> 6) * 72 + (s & 63);   // padded storage index
        const int lane = tid & 31;
        const int wrp  = tid >> 5;

        // E column half (64 k-values) in fp16, packed half2 (32 regs).
        half2 E2h[32];
        #pragma unroll 8
        for (int j = 0; j < 32; ++j) {
            const int k = kh * 64 + 2 * j;
            E2h[j] = __floats2half2_rn(expf(trans[k * SS + s]),
                                       expf(trans[(k + 1) * SS + s]));
        }
        const int lab = dlab[s];
        const float* lp_base = nnet + (long long)n * TT * FF + lab;
        float lp  = __ldg(lp_base);                          // t = 0
        float lp1 = __ldg(lp_base + FF);                     // t = 1

        // init: stored v = true v * 2^-7 (anchor 2^-7); Mexp starts at 7
        if (!kh) sh_vh[0][pidx] = __float2half_rn((s == 0) ? 0.0078125f : 0.0f);
        if (tid < 8) {
            sh_wmax[0][tid] = 8u << 10;     // fp16 bits of 2^-7 -> sigma = 1
            sh_wmax[1][tid] = 8u << 10;
        }
        __syncthreads();

        int cur  = 0;
        int Mexp = 7;

        #pragma unroll 2
        for (int t = 0; t < nf; ++t) {
            // even steps: exact 2^k rescale keyed to the block max written by
            // the previous (odd) step; odd steps: sigma = 1.
            float ps;
            if ((t & 1) == 0) {
                unsigned m = sh_wmax[cur][0];
                #pragma unroll
                for (int w = 1; w < 8; ++w) m = max(m, sh_wmax[cur][w]);
                const int   eh    = (int)(m >> 10);         // fp16 biased exp
                const float sigma = __uint_as_float((unsigned)(135 - eh) << 23);
                Mexp += eh - 8;
                ps = __expf(lp) * sigma;
            } else {
                ps = __expf(lp);
            }
            const __half ps_h = __float2half_rn(ps);   // off critical path

            const int   tn   = (t + 2 < TT) ? (t + 2) : (TT - 1);
            const float lpn2 = __ldg(lp_base + (long long)tn * FF); // prefetch

            // batch-load this thread's 64-half v segment (8 x LDS.128)
            const uint4* vp =
                reinterpret_cast<const uint4*>(&sh_vh[cur][kh * 72]);
            uint4 q[8];
            #pragma unroll
            for (int i = 0; i < 8; ++i) q[i] = vp[i];

            // 32 HFMA2 across 4 half2 accumulators
            half2 a0 = __float2half2_rn(0.f), a1 = a0, a2 = a0, a3 = a0;
            #pragma unroll
            for (int i = 0; i < 8; ++i) {
                const int bb = i * 4;
                const half2 v0 = *reinterpret_cast<const half2*>(&q[i].x);
                const half2 v1 = *reinterpret_cast<const half2*>(&q[i].y);
                const half2 v2 = *reinterpret_cast<const half2*>(&q[i].z);
                const half2 v3 = *reinterpret_cast<const half2*>(&q[i].w);
                a0 = __hfma2(v0, E2h[bb + 0], a0);
                a1 = __hfma2(v1, E2h[bb + 1], a1);
                a2 = __hfma2(v2, E2h[bb + 2], a2);
                a3 = __hfma2(v3, E2h[bb + 3], a3);
            }
            // tree -> pair combine (SHFL) -> hmul -> store
            const half2 s01 = __hadd2(a0, a1);
            const half2 s23 = __hadd2(a2, a3);
            const half2 sal = __hadd2(s01, s23);
            __half hsum = __hadd(__low2half(sal), __high2half(sal));
            const unsigned other =
                __shfl_xor_sync(0xffffffffu,
                                (unsigned)__half_as_ushort(hsum), 1);
            hsum = __hadd(hsum, __ushort_as_half((unsigned short)other));
            const __half accv = __hmul(hsum, ps_h);

            if (!kh) sh_vh[cur ^ 1][pidx] = accv;

            if (t & 1) {   // odd steps: publish warp max for next even step
                const unsigned hb = (unsigned)__half_as_ushort(accv);
                const unsigned wm = __reduce_max_sync(0xffffffffu, hb);
                if (lane == 0) sh_wmax[cur ^ 1][wrp] = wm;
            }

            lp  = lp1;
            lp1 = lpn2;
            __syncthreads();
            cur ^= 1;
        }

        // den = Mexp*ln2 + log(sum stored v)
        if (tid < 128) {
            float v = __half2float(sh_vh[cur][(tid >> 6) * 72 + (tid & 63)]);
            #pragma unroll
            for (int o = 16; o; o >>= 1) v += __shfl_xor_sync(0xffffffffu, v, o);
            if ((tid & 31) == 0) sh_wsum[tid >> 5] = v;
        }
        __syncthreads();
        if (tid == 0) {
            const float sv = sh_wsum[0] + sh_wsum[1] + sh_wsum[2] + sh_wsum[3];
            g_den[n] = (float)((double)Mexp * 0.6931471805599453 +
                               (double)logf(sv));
        }
    } else {
        // ============ numerator forward (log space), 2 states/thread ==========
        if (tid >= 128) return;
        const int n  = b - NN;
        const int nf = sup[n * 3 + 2];
        const int qi = nlens[n];
        const int i  = tid;                 // 0..127; active i < 100

        // thread i owns states l0 = 2i+1 and l1 = 2i+2
        const float* lpb0 = nnet;  // dummy init
        const float* lpb1 = nnet;
        float lpA = 0.f, lpA1 = 0.f, lpB = 0.f, lpB1 = 0.f;

        if (i < 100) {
            const long long base = (long long)n * TT * FF;
            lpb0 = nnet + base + nlab[n * LL + 2 * i];       // emit for l0
            lpb1 = nnet + base + nlab[n * LL + 2 * i + 1];   // emit for l1
            lpA  = __ldg(lpb0);       lpB  = __ldg(lpb1);
            lpA1 = __ldg(lpb0 + FF);  lpB1 = __ldg(lpb1 + FF);
        }
        for (int j = i; j <= LL; j += 128) {
            sh_a[0][j] = (j == 0) ? 0.0f : NEGF;
            sh_a[1][j] = NEGF;
        }
        int cur = 0;
        __syncthreads();

        for (int t = 0; t < nf; ++t) {
            if (i < 100) {
                const float am = sh_a[cur][2 * i];       // old alpha[l0-1]
                const float a0 = sh_a[cur][2 * i + 1];   // old alpha[l0]
                const float a1 = sh_a[cur][2 * i + 2];   // old alpha[l1]

                const float h0 = fmaxf(a0, am), l0v = fminf(a0, am);
                const float nv0 = h0 + __logf(1.0f + __expf(l0v - h0)) + lpA;
                const float h1 = fmaxf(a1, a0), l1v = fminf(a1, a0);
                const float nv1 = h1 + __logf(1.0f + __expf(l1v - h1)) + lpB;

                const int   tn = (t + 2 < TT) ? (t + 2) : (TT - 1);
                const float pA = __ldg(lpb0 + (long long)tn * FF);
                const float pB = __ldg(lpb1 + (long long)tn * FF);

                sh_a[cur ^ 1][2 * i + 1] = nv0;
                sh_a[cur ^ 1][2 * i + 2] = nv1;
                if (i == 0) sh_a[cur ^ 1][0] = NEGF;     // alpha[0] = NEG each step
                lpA = lpA1; lpA1 = pA;
                lpB = lpB1; lpB1 = pB;
            }
            __syncthreads();
            cur ^= 1;
        }
        if (i == 0) g_num[n] = sh_a[cur][qi];
    }
}

__global__ void mmi_finalize(const int* __restrict__ sup, float* __restrict__ out)
{
    const int tid = threadIdx.x;  // 32 threads
    float tot = 0.f, fr = 0.f, af = 0.f;
    if (tid < NN) {
        const int nf = sup[tid * 3 + 2];
        const float t = g_num[tid] - g_den[tid];
        const bool fin = isfinite(t) && (t > 0.5f * NEGF);
        tot = fin ? t : 0.f;
        fr  = fin ? (float)nf : 0.f;
        af  = (float)nf;
    }
    #pragma unroll
    for (int o = 16; o; o >>= 1) {
        tot += __shfl_xor_sync(0xffffffffu, tot, o);
        fr  += __shfl_xor_sync(0xffffffffu, fr, o);
        af  += __shfl_xor_sync(0xffffffffu, af, o);
    }
    if (tid == 0) {
        out[0] = tot;
        out[1] = fr;
        out[2] = af;
    }
}

extern "C" void kernel_launch(void* const* d_in, const int* in_sizes, int n_in,
                              void* d_out, int out_size)
{
    const float* nnet  = (const float*)d_in[0];
    const int*   sup   = (const int*)  d_in[1];
    const float* trans = (const float*)d_in[2];
    const int*   dlab  = (const int*)  d_in[3];
    const int*   nlab  = (const int*)  d_in[4];
    const int*   nlens = (const int*)  d_in[5];

    mmi_forward<<<2 * NN, 256>>>(nnet, sup, trans, dlab, nlab, nlens);
    mmi_finalize<<<1, 32>>>(sup, (float*)d_out);
}